// round 14
// baseline (speedup 1.0000x reference)
#include <cuda_runtime.h>

// BayesianFlowNetworkDiscretised R13: TN=256 table (1 build block/row, faster
// PDL producer), EPT=4 main (float4 mu, 4 gathers in flight, half the warps).

constexpr int K   = 16;
constexpr int H   = 16;
constexpr int TPB = 256;
constexpr int EPT = 4;                 // elements per thread (main)
constexpr int EPB = TPB * EPT;         // 1024 elements per block
constexpr int TN  = 256;               // table entries per row
constexpr int BMAX = 64;
#define M_LO (-6.5f)
#define M_HI (6.5f)

__device__ float4 g_tab[BMAX * TN];    // (zb, dzb, st, dst)

__device__ __forceinline__ float tanh_approx(float x) {
    float y;
    asm("tanh.approx.f32 %0, %1;" : "=f"(y) : "f"(x));
    return y;
}

// erf(z) ~= tanh(z*(C0+C1 s+C2 s^2+C3 s^3)), s=min(z^2,SCAP); max abs err ~7e-5
#define ERF_C0 1.1283792f
#define ERF_C1 0.1038252f
#define ERF_C2 (-0.00176024f)
#define ERF_C3 (-2.46588e-5f)
#define ERF_SCAP 15.3664f

__device__ __forceinline__ float erf_c(float z) {
    const float s = fminf(z * z, ERF_SCAP);
    const float p = fmaf(fmaf(fmaf(ERF_C3, s, ERF_C2), s, ERF_C1), s, ERF_C0);
    return tanh_approx(z * p);
}

// ---------------- build kernel ----------------

struct RowConst { float inv_gamma, vs, a0, be0, a1, be1; bool tmin; };

__device__ __forceinline__ float2 eval_g(float m, const float4* sp, const RowConst& rc) {
    float acc0 = fmaf(m, rc.be0, rc.a0);
    float acc1 = fmaf(m, rc.be1, rc.a1);
#pragma unroll
    for (int j = 0; j < H; j++) {
        const float4 p = sp[j];
        const float a = fmaf(m, p.x, p.y);
        const float inner = a * fmaf(0.0356774081f, a * a, 0.7978845608f);
        const float ath = a * tanh_approx(inner);
        acc0 = fmaf(ath, p.z, acc0);
        acc1 = fmaf(ath, p.w, acc1);
    }
    float mu_x = fmaf(m, rc.inv_gamma, -rc.vs * acc0);
    float ln   = fminf(fmaxf(acc1, -10.0f), 10.0f);
    float sg   = fmaxf(rc.vs * __expf(ln), 0.02f);
    if (rc.tmin) { mu_x = 0.0f; sg = 1.0f; }
    const float inv = __fdividef(0.70710678118654752f, sg);
    return make_float2((-1.0f - mu_x) * inv, 0.125f * inv);
}

__global__ __launch_bounds__(TPB) void build_table(
    const float* __restrict__ t,
    const float* __restrict__ W1,
    const float* __restrict__ b1,
    const float* __restrict__ W2,
    const float* __restrict__ b2)
{
    __shared__ float4 s_pack[H];
    __shared__ float  s_scal[8];
    __shared__ float2 s_e[TN];
    const int b = blockIdx.x;            // one block per row

    if (threadIdx.x < H) {
        const int j = threadIdx.x;
        const float tv = t[b];
        s_pack[j] = make_float4(W1[j],
                                fmaf(tv, W1[H + j], b1[j]),
                                0.5f * W2[2 * j],
                                0.5f * W2[2 * j + 1]);
        if (j == 0) {
            const float g = 1.0f - exp2f(2.0f * tv * -5.6438561897747395f);
            s_scal[0] = 1.0f / g;
            s_scal[1] = sqrtf((1.0f - g) / g);
            s_scal[2] = (tv < 1e-6f) ? 1.0f : 0.0f;
        }
    }
    __syncthreads();
    if (threadIdx.x == 0) {
        float a0 = b2[0], a1v = b2[1], be0 = 0.0f, be1 = 0.0f;
#pragma unroll
        for (int j = 0; j < H; j++) {
            const float4 p = s_pack[j];
            a0  = fmaf(p.y, p.z, a0);
            a1v = fmaf(p.y, p.w, a1v);
            be0 = fmaf(p.x, p.z, be0);
            be1 = fmaf(p.x, p.w, be1);
        }
        s_scal[3] = a0;  s_scal[4] = be0;
        s_scal[5] = a1v; s_scal[6] = be1;
    }
    __syncthreads();

    RowConst rc;
    rc.inv_gamma = s_scal[0]; rc.vs = s_scal[1];
    rc.tmin = s_scal[2] > 0.5f;
    rc.a0 = s_scal[3]; rc.be0 = s_scal[4];
    rc.a1 = s_scal[5]; rc.be1 = s_scal[6];

    const float dm = (M_HI - M_LO) / (float)(TN - 1);
    const int i = threadIdx.x;           // TN == TPB: one entry per thread
    const float m0 = M_LO + dm * (float)i;
    const float2 g0 = eval_g(m0, s_pack, rc);
    s_e[i] = g0;
    __syncthreads();
    float2 g1 = (i < TN - 1) ? s_e[i + 1] : eval_g(m0 + dm, s_pack, rc);
    g_tab[b * TN + i] = make_float4(g0.x, g1.x - g0.x, g0.y, g1.y - g0.y);

#if __CUDA_ARCH__ >= 900
    cudaTriggerProgrammaticLaunchCompletion();
#endif
}

// ---------------- main kernel ----------------

__global__ __launch_bounds__(TPB) void bfn_main(
    const float* __restrict__ mu,
    float* __restrict__ out,
    int Dn)
{
    __shared__ float2 s_zs[EPB];

    const int b = blockIdx.y;
    const int blk0 = blockIdx.x * EPB;
    const int tid  = threadIdx.x;
    const int lane = tid & 31;
    const int wid  = tid >> 5;

    // u = m*SA + SB (single FFMA)
    const float SA = (float)(TN - 1) / (M_HI - M_LO);
    const float SB = -M_LO * SA;
    const float4* tab = g_tab + b * TN;

    const int d0 = blk0 + tid * EPT;
    const bool full_blk = (blk0 + EPB <= Dn);

    if (full_blk) {
        // mu load issued BEFORE the grid-dependency wait (overlap under PDL)
        const float4 mv = *reinterpret_cast<const float4*>(
            mu + (size_t)b * Dn + d0);
#if __CUDA_ARCH__ >= 900
        cudaGridDependencySynchronize();
#endif
        const float mm[EPT] = {mv.x, mv.y, mv.z, mv.w};
#pragma unroll
        for (int e = 0; e < EPT; e++) {
            float u = fmaf(mm[e], SA, SB);
            u = fminf(fmaxf(u, 0.0f), (float)(TN - 1) - 1e-3f);
            const int   idx = __float2int_rd(u);
            const float fr  = u - (float)idx;
            const float4 en = __ldg(&tab[idx]);
            s_zs[tid * EPT + e] = make_float2(fmaf(fr, en.y, en.x),
                                              fmaf(fr, en.w, en.z));
        }
        __syncwarp();

        const int q = lane & 3;
        const float kq = (float)(q << 2);
        const float k1 = kq + 1.0f, k2 = kq + 2.0f, k3 = kq + 3.0f, k4 = kq + 4.0f;
        const bool q0 = (q == 0), q3 = (q == 3);
        const int we0 = wid * (EPT * 32);            // warp's first elem (128)
        float4* wout = reinterpret_cast<float4*>(out)
                     + ((size_t)b * Dn + blk0 + we0) * 4 + lane;
        const int src = we0 + (lane >> 2);

#pragma unroll
        for (int it = 0; it < 4 * EPT; it++) {       // 16 iterations
            const float2 zs = s_zs[src + it * 8];
            const float zb = zs.x, st = zs.y;

            const float e1 = erf_c(fmaf(st, k1, zb));
            const float e2 = erf_c(fmaf(st, k2, zb));
            const float e3 = erf_c(fmaf(st, k3, zb));
            float e4 = erf_c(fmaf(st, k4, zb));
            if (q3) e4 = 1.0f;                       // upper edge exact

            const float eup = __shfl_up_sync(0xffffffffu, e4, 1);
            const float e0 = q0 ? -1.0f : eup;       // lower edge exact

            wout[it * 32] = make_float4(0.5f * (e1 - e0), 0.5f * (e2 - e1),
                                        0.5f * (e3 - e2), 0.5f * (e4 - e3));
        }
    } else {
#if __CUDA_ARCH__ >= 900
        cudaGridDependencySynchronize();
#endif
        for (int e = 0; e < EPT; e++) {
            const int d = d0 + e;
            if (d >= Dn) break;
            const float m = mu[(size_t)b * Dn + d];
            float u = fmaf(m, SA, SB);
            u = fminf(fmaxf(u, 0.0f), (float)(TN - 1) - 1e-3f);
            const int   idx = __float2int_rd(u);
            const float fr  = u - (float)idx;
            const float4 en = __ldg(&tab[idx]);
            const float zbase = fmaf(fr, en.y, en.x);
            const float step  = fmaf(fr, en.w, en.z);

            float h[K - 1];
#pragma unroll
            for (int j = 0; j < K - 1; j++)
                h[j] = 0.5f * erf_c(fmaf(step, (float)(j + 1), zbase));
            float r[K];
            r[0] = h[0] + 0.5f;
#pragma unroll
            for (int j = 1; j < K - 1; j++) r[j] = h[j] - h[j - 1];
            r[K - 1] = 0.5f - h[K - 2];
            float4* o = reinterpret_cast<float4*>(out + ((size_t)b * Dn + d) * K);
            o[0] = make_float4(r[0],  r[1],  r[2],  r[3]);
            o[1] = make_float4(r[4],  r[5],  r[6],  r[7]);
            o[2] = make_float4(r[8],  r[9],  r[10], r[11]);
            o[3] = make_float4(r[12], r[13], r[14], r[15]);
        }
    }
}

extern "C" void kernel_launch(void* const* d_in, const int* in_sizes, int n_in,
                              void* d_out, int out_size) {
    const float* mu = (const float*)d_in[0];
    const float* t  = (const float*)d_in[1];
    const float* W1 = (const float*)d_in[2];
    const float* b1 = (const float*)d_in[3];
    const float* W2 = (const float*)d_in[4];
    const float* b2 = (const float*)d_in[5];
    float* out = (float*)d_out;

    const int B = in_sizes[1];           // t has B elements
    const int D = in_sizes[0] / B;       // mu is [B, D]
    const int Bc = (B <= BMAX) ? B : BMAX;

    build_table<<<Bc, TPB>>>(t, W1, b1, W2, b2);   // one block per row

    dim3 grid((D + EPB - 1) / EPB, B);

    cudaLaunchConfig_t cfg = {};
    cfg.gridDim = grid;
    cfg.blockDim = dim3(TPB, 1, 1);
    cfg.dynamicSmemBytes = 0;
    cfg.stream = 0;
    cudaLaunchAttribute attrs[1];
    attrs[0].id = cudaLaunchAttributeProgrammaticStreamSerialization;
    attrs[0].val.programmaticStreamSerializationAllowed = 1;
    cfg.attrs = attrs;
    cfg.numAttrs = 1;
    cudaError_t err = cudaLaunchKernelEx(&cfg, bfn_main, mu, out, D);
    if (err != cudaSuccess) {
        (void)cudaGetLastError();
        bfn_main<<<grid, TPB>>>(mu, out, D);
    }
}

// round 16
// speedup vs baseline: 1.1001x; 1.1001x over previous
#include <cuda_runtime.h>

// BayesianFlowNetworkDiscretised R15 (= R14 resubmit): fully fused single
// kernel. Each block rebuilds its row's 256-entry (zbase,step) table in smem
// (1 eval/thread), then table-lookup + coalesced erf epilogue. Removes the
// persistent ~6us two-kernel gap. (R14 bench died to a container flake.)

constexpr int K   = 16;
constexpr int H   = 16;
constexpr int TPB = 256;
constexpr int EPT = 2;                 // elements per thread
constexpr int EPB = TPB * EPT;         // 512 elements per block
constexpr int TN  = 256;               // table entries per row (== TPB)
#define M_LO (-6.5f)
#define M_HI (6.5f)

__device__ __forceinline__ float tanh_approx(float x) {
    float y;
    asm("tanh.approx.f32 %0, %1;" : "=f"(y) : "f"(x));
    return y;
}

// erf(z) ~= tanh(z*(C0+C1 s+C2 s^2+C3 s^3)), s=min(z^2,SCAP); max abs err ~7e-5
#define ERF_C0 1.1283792f
#define ERF_C1 0.1038252f
#define ERF_C2 (-0.00176024f)
#define ERF_C3 (-2.46588e-5f)
#define ERF_SCAP 15.3664f

__device__ __forceinline__ float erf_c(float z) {
    const float s = fminf(z * z, ERF_SCAP);
    const float p = fmaf(fmaf(fmaf(ERF_C3, s, ERF_C2), s, ERF_C1), s, ERF_C0);
    return tanh_approx(z * p);
}

struct RowConst { float inv_gamma, vs, a0, be0, a1, be1; bool tmin; };

__device__ __forceinline__ float2 eval_g(float m, const float4* sp, const RowConst& rc) {
    float acc0 = fmaf(m, rc.be0, rc.a0);
    float acc1 = fmaf(m, rc.be1, rc.a1);
#pragma unroll
    for (int j = 0; j < H; j++) {
        const float4 p = sp[j];
        const float a = fmaf(m, p.x, p.y);
        const float inner = a * fmaf(0.0356774081f, a * a, 0.7978845608f);
        const float ath = a * tanh_approx(inner);
        acc0 = fmaf(ath, p.z, acc0);
        acc1 = fmaf(ath, p.w, acc1);
    }
    float mu_x = fmaf(m, rc.inv_gamma, -rc.vs * acc0);
    float ln   = fminf(fmaxf(acc1, -10.0f), 10.0f);
    float sg   = fmaxf(rc.vs * __expf(ln), 0.02f);
    if (rc.tmin) { mu_x = 0.0f; sg = 1.0f; }
    const float inv = __fdividef(0.70710678118654752f, sg);
    return make_float2((-1.0f - mu_x) * inv, 0.125f * inv);
}

__global__ __launch_bounds__(TPB) void bfn_fused(
    const float* __restrict__ mu,
    const float* __restrict__ t,
    const float* __restrict__ W1,
    const float* __restrict__ b1,
    const float* __restrict__ W2,
    const float* __restrict__ b2,
    float* __restrict__ out,
    int Dn)
{
    __shared__ float4 s_pack[H];   // {W1[0][j], t*W1[1][j]+b1[j], .5*W2[j][0], .5*W2[j][1]}
    __shared__ float  s_scal[8];   // inv_gamma, vs, tmin, a0, be0, a1, be1
    __shared__ float2 s_g[TN];     // raw (zbase, step) at grid points
    __shared__ float2 s_zs[EPB];   // per-element (zbase, step)

    const int b    = blockIdx.y;
    const int blk0 = blockIdx.x * EPB;
    const int tid  = threadIdx.x;
    const int lane = tid & 31;
    const int wid  = tid >> 5;

    const int d0 = blk0 + tid * EPT;
    const bool full_blk = (blk0 + EPB <= Dn);

    // issue mu load first: DRAM latency hides under the table build
    float2 mv = make_float2(0.0f, 0.0f);
    float m_tail[EPT] = {0.0f, 0.0f};
    if (full_blk) {
        mv = *reinterpret_cast<const float2*>(mu + (size_t)b * Dn + d0);
    } else {
        for (int e = 0; e < EPT; e++)
            if (d0 + e < Dn) m_tail[e] = mu[(size_t)b * Dn + d0 + e];
    }

    // ---- weights + row constants ----
    if (tid < H) {
        const int j = tid;
        const float tv = t[b];
        const float w1a = W1[j];
        const float w1b = W1[H + j];
        const float b1v = b1[j];
        const float w2a = W2[2 * j];
        const float w2b = W2[2 * j + 1];
        s_pack[j] = make_float4(w1a, fmaf(tv, w1b, b1v), 0.5f * w2a, 0.5f * w2b);
        if (j == 0) {
            const float g = 1.0f - exp2f(2.0f * tv * -5.6438561897747395f);
            s_scal[0] = 1.0f / g;
            s_scal[1] = sqrtf((1.0f - g) / g);
            s_scal[2] = (tv < 1e-6f) ? 1.0f : 0.0f;
        }
    }
    __syncthreads();
    if (tid == 0) {
        float a0 = b2[0], a1v = b2[1], be0 = 0.0f, be1 = 0.0f;
#pragma unroll
        for (int j = 0; j < H; j++) {
            const float4 p = s_pack[j];
            a0  = fmaf(p.y, p.z, a0);
            a1v = fmaf(p.y, p.w, a1v);
            be0 = fmaf(p.x, p.z, be0);
            be1 = fmaf(p.x, p.w, be1);
        }
        s_scal[3] = a0;  s_scal[4] = be0;
        s_scal[5] = a1v; s_scal[6] = be1;
    }
    __syncthreads();

    // ---- build table in smem: one eval per thread (TN == TPB) ----
    {
        RowConst rc;
        rc.inv_gamma = s_scal[0]; rc.vs = s_scal[1];
        rc.tmin = s_scal[2] > 0.5f;
        rc.a0 = s_scal[3]; rc.be0 = s_scal[4];
        rc.a1 = s_scal[5]; rc.be1 = s_scal[6];
        const float dm = (M_HI - M_LO) / (float)(TN - 1);
        s_g[tid] = eval_g(fmaf(dm, (float)tid, M_LO), s_pack, rc);
    }
    __syncthreads();

    // ---- phase 1: per-element lookup (linear interp between idx, idx+1) ----
    const float SA = (float)(TN - 1) / (M_HI - M_LO);
    const float SB = -M_LO * SA;

    if (full_blk) {
#pragma unroll
        for (int e = 0; e < EPT; e++) {
            const float m = (e == 0) ? mv.x : mv.y;
            float u = fmaf(m, SA, SB);
            u = fminf(fmaxf(u, 0.0f), (float)(TN - 1) - 1e-3f);
            const int   idx = __float2int_rd(u);
            const float fr  = u - (float)idx;
            const float2 g0 = s_g[idx];
            const float2 g1 = s_g[idx + 1];
            s_zs[tid * EPT + e] = make_float2(fmaf(fr, g1.x - g0.x, g0.x),
                                              fmaf(fr, g1.y - g0.y, g0.y));
        }
        __syncwarp();

        // ---- phase 2: warp-remapped coalesced erf epilogue ----
        const int q = lane & 3;
        const float kq = (float)(q << 2);
        const float k1 = kq + 1.0f, k2 = kq + 2.0f, k3 = kq + 3.0f, k4 = kq + 4.0f;
        const bool q0 = (q == 0), q3 = (q == 3);
        const int we0 = wid * 64;                    // warp's first elem in block
        float4* wout = reinterpret_cast<float4*>(out)
                     + ((size_t)b * Dn + blk0 + we0) * 4 + lane;
        const int src = we0 + (lane >> 2);

#pragma unroll
        for (int it = 0; it < 8; it++) {
            const float2 zs = s_zs[src + it * 8];
            const float zb = zs.x, st = zs.y;

            const float e1 = erf_c(fmaf(st, k1, zb));
            const float e2 = erf_c(fmaf(st, k2, zb));
            const float e3 = erf_c(fmaf(st, k3, zb));
            float e4 = erf_c(fmaf(st, k4, zb));
            if (q3) e4 = 1.0f;                       // upper edge exact

            const float eup = __shfl_up_sync(0xffffffffu, e4, 1);
            const float e0 = q0 ? -1.0f : eup;       // lower edge exact

            wout[it * 32] = make_float4(0.5f * (e1 - e0), 0.5f * (e2 - e1),
                                        0.5f * (e3 - e2), 0.5f * (e4 - e3));
        }
    } else {
        // tail block (not taken when D % EPB == 0)
        for (int e = 0; e < EPT; e++) {
            const int d = d0 + e;
            const bool ok = (d < Dn);
            const float m = m_tail[e];
            float u = fmaf(m, SA, SB);
            u = fminf(fmaxf(u, 0.0f), (float)(TN - 1) - 1e-3f);
            const int   idx = __float2int_rd(u);
            const float fr  = u - (float)idx;
            const float2 g0 = s_g[idx];
            const float2 g1 = s_g[idx + 1];
            const float zbase = fmaf(fr, g1.x - g0.x, g0.x);
            const float step  = fmaf(fr, g1.y - g0.y, g0.y);

            float h[K - 1];
#pragma unroll
            for (int j = 0; j < K - 1; j++)
                h[j] = 0.5f * erf_c(fmaf(step, (float)(j + 1), zbase));
            float r[K];
            r[0] = h[0] + 0.5f;
#pragma unroll
            for (int j = 1; j < K - 1; j++) r[j] = h[j] - h[j - 1];
            r[K - 1] = 0.5f - h[K - 2];
            if (ok) {
                float4* o = reinterpret_cast<float4*>(out + ((size_t)b * Dn + d) * K);
                o[0] = make_float4(r[0],  r[1],  r[2],  r[3]);
                o[1] = make_float4(r[4],  r[5],  r[6],  r[7]);
                o[2] = make_float4(r[8],  r[9],  r[10], r[11]);
                o[3] = make_float4(r[12], r[13], r[14], r[15]);
            }
        }
    }
}

extern "C" void kernel_launch(void* const* d_in, const int* in_sizes, int n_in,
                              void* d_out, int out_size) {
    const float* mu = (const float*)d_in[0];
    const float* t  = (const float*)d_in[1];
    const float* W1 = (const float*)d_in[2];
    const float* b1 = (const float*)d_in[3];
    const float* W2 = (const float*)d_in[4];
    const float* b2 = (const float*)d_in[5];
    float* out = (float*)d_out;

    const int B = in_sizes[1];           // t has B elements
    const int D = in_sizes[0] / B;       // mu is [B, D]

    dim3 grid((D + EPB - 1) / EPB, B);
    bfn_fused<<<grid, TPB>>>(mu, t, W1, b1, W2, b2, out, D);
}